// round 1
// baseline (speedup 1.0000x reference)
#include <cuda_runtime.h>
#include <cuda_bf16.h>

// PlotLine2: rasterize 2D polylines as sums of Gaussian outer products.
// Exploits: rounded coords are integers -> Gaussian support is 11 taps;
// histogram + separable 11-tap convolution replaces the dense einsum.

#define N_IMG   128
#define P_PTS   16
#define S_IMG   128
#define D_RAD   5
#define NTAP    (2 * D_RAD + 1)            // 11
#define CP_ROWS (S_IMG + 1)                // 129 histogram rows (x = 0..128)
#define CP_COLS (S_IMG + 1 + 2 * D_RAD)    // 139 (y padded by D on both sides)
#define TP_ROWS (S_IMG + 1 + 2 * D_RAD)    // 139 (x padded by D on both sides)
#define TP_COLS S_IMG                      // 128
#define THREADS 256

__global__ __launch_bounds__(THREADS, 1)
void plotline2_kernel(const float* __restrict__ points, float* __restrict__ out) {
    extern __shared__ float sm[];
    float* CP  = sm;                               // [CP_ROWS][CP_COLS] histogram (col = y + D_RAD)
    float* TP  = CP + CP_ROWS * CP_COLS;           // [TP_ROWS][TP_COLS] y-convolved (row = x + D_RAD)
    float* pts = TP + TP_ROWS * TP_COLS;           // [2*P_PTS]

    const int tid = threadIdx.x;
    const int n   = blockIdx.x;

    // ---- Phase 0: zero smem, stage control points ----
    for (int i = tid; i < CP_ROWS * CP_COLS + TP_ROWS * TP_COLS; i += THREADS)
        sm[i] = 0.0f;
    if (tid < 2 * P_PTS)
        pts[tid] = points[n * (2 * P_PTS) + tid];
    __syncthreads();

    // Gaussian taps: w[k] = exp(-(k-D)^2)
    float w[NTAP];
#pragma unroll
    for (int k = 0; k < NTAP; k++) {
        int d = k - D_RAD;
        w[k] = expf(-(float)(d * d));
    }

    // ---- Phase 1: histogram of rounded lerp points ----
    // Exact replication of reference arithmetic:
    //   t = i/128 (exact), 1-t exact, then non-contracted mul/mul/add in fp32,
    //   rintf = round-to-nearest-even (matches jnp.round).
    for (int idx = tid; idx < (P_PTS - 1) * S_IMG; idx += THREADS) {
        int seg = idx >> 7;            // / S_IMG
        int i   = idx & (S_IMG - 1);
        float t   = (float)i * (1.0f / (float)S_IMG);
        float omt = 1.0f - t;
        float p0x = pts[seg * 2 + 0], p0y = pts[seg * 2 + 1];
        float p1x = pts[seg * 2 + 2], p1y = pts[seg * 2 + 3];
        float x = __fadd_rn(__fmul_rn(omt, p0x), __fmul_rn(t, p1x));
        float y = __fadd_rn(__fmul_rn(omt, p0y), __fmul_rn(t, p1y));
        int ix = (int)rintf(x);        // 0..128
        int iy = (int)rintf(y);        // 0..128
        atomicAdd(&CP[ix * CP_COLS + iy + D_RAD], 1.0f);
    }
    __syncthreads();

    // ---- Phase 2: convolve along y ----
    // TP[x + D][t] = sum_k w[k] * CP[x][t + k]   (k spans dy = -D..D)
    for (int idx = tid; idx < CP_ROWS * S_IMG; idx += THREADS) {
        int x = idx >> 7;
        int t = idx & (S_IMG - 1);
        const float* row = &CP[x * CP_COLS + t];
        float acc = 0.0f;
#pragma unroll
        for (int k = 0; k < NTAP; k++)
            acc = fmaf(w[k], row[k], acc);
        TP[(x + D_RAD) * TP_COLS + t] = acc;
    }
    __syncthreads();

    // ---- Phase 3: convolve along x, tanh, write ----
    float* o = out + n * (S_IMG * S_IMG);
    for (int idx = tid; idx < S_IMG * S_IMG; idx += THREADS) {
        int s = idx >> 7;
        int t = idx & (S_IMG - 1);
        float acc = 0.0f;
#pragma unroll
        for (int k = 0; k < NTAP; k++)
            acc = fmaf(w[k], TP[(s + k) * TP_COLS + t], acc);
        o[idx] = tanhf(acc);
    }
}

extern "C" void kernel_launch(void* const* d_in, const int* in_sizes, int n_in,
                              void* d_out, int out_size) {
    const float* points = (const float*)d_in[0];
    float* out = (float*)d_out;
    size_t smem = (size_t)(CP_ROWS * CP_COLS + TP_ROWS * TP_COLS + 2 * P_PTS) * sizeof(float);
    cudaFuncSetAttribute(plotline2_kernel,
                         cudaFuncAttributeMaxDynamicSharedMemorySize, (int)smem);
    plotline2_kernel<<<N_IMG, THREADS, smem>>>(points, out);
}

// round 5
// speedup vs baseline: 1.0345x; 1.0345x over previous
#include <cuda_runtime.h>
#include <cuda_bf16.h>

// PlotLine2: histogram of rounded lerp points + separable 11-tap Gaussian conv.
// R1 -> R2: transposed layouts + register sliding-window conv (1.6 LDS/output),
// 512 threads, constant-immediate taps, MUFU.TANH epilogue.

#define N_IMG    128
#define P_PTS    16
#define S_IMG    128
#define D_RAD    5
#define NTAP     11
#define CPT_ROWS 139          // y_pad = y + 5, rows 0..138
#define CPT_COLS 129          // x = 0..128
#define CPT_SIZE 17932        // 139*129 = 17931, padded to multiple of 4
#define V_ROWS   128          // t = 0..127
#define V_COLS   139          // x_pad = x + 5 (odd stride -> conflict-free)
#define V_SIZE   (V_ROWS * V_COLS)   // 17792
#define THREADS  512
#define NWARP    (THREADS / 32)
#define CHUNK    16

__device__ __forceinline__ float tanh_approx(float x) {
    float r;
    asm("tanh.approx.f32 %0, %1;" : "=f"(r) : "f"(x));
    return r;
}

__global__ __launch_bounds__(THREADS, 1)
void plotline2_kernel(const float* __restrict__ points, float* __restrict__ out) {
    extern __shared__ float sm[];
    float* CPT = sm;                    // [CPT_ROWS][CPT_COLS] histogram, transposed (row = y+5)
    float* V   = sm + CPT_SIZE;        // [V_ROWS][V_COLS] y-convolved (col = x+5)
    float* pts = V + V_SIZE;           // [2*P_PTS]

    const int tid = threadIdx.x;
    const int n   = blockIdx.x;
    const int w   = tid >> 5;
    const int lane = tid & 31;

    // ---- Phase 0: zero smem (vectorized), stage control points ----
    {
        float4* z = (float4*)sm;
        const float4 z4 = make_float4(0.f, 0.f, 0.f, 0.f);
        for (int i = tid; i < (CPT_SIZE + V_SIZE) / 4; i += THREADS) z[i] = z4;
    }
    if (tid < 2 * P_PTS) pts[tid] = points[n * (2 * P_PTS) + tid];
    __syncthreads();

    // ---- Phase 1: histogram of rounded lerp points (exact ref arithmetic) ----
    for (int idx = tid; idx < (P_PTS - 1) * S_IMG; idx += THREADS) {
        int seg = idx >> 7;
        int i   = idx & (S_IMG - 1);
        float t   = (float)i * (1.0f / (float)S_IMG);
        float omt = 1.0f - t;
        float x = __fadd_rn(__fmul_rn(omt, pts[seg * 2 + 0]), __fmul_rn(t, pts[seg * 2 + 2]));
        float y = __fadd_rn(__fmul_rn(omt, pts[seg * 2 + 1]), __fmul_rn(t, pts[seg * 2 + 3]));
        int ix = (int)rintf(x);     // 0..128
        int iy = (int)rintf(y);     // 0..128
        atomicAdd(&CPT[(iy + D_RAD) * CPT_COLS + ix], 1.0f);
    }
    __syncthreads();

    // Compile-time Gaussian taps -> FFMA immediate form
    const float W[NTAP] = {
        1.3887943864964021e-11f, 1.1253517471925912e-7f, 1.2340980408667956e-4f,
        1.8315638888734179e-2f,  0.36787944117144233f,   1.0f,
        0.36787944117144233f,    1.8315638888734179e-2f, 1.2340980408667956e-4f,
        1.1253517471925912e-7f,  1.3887943864964021e-11f
    };

    // ---- Phase 2: convolve along y ----
    // V[t][x+5] = sum_k W[k] * CPT[t+k][x]
    // Task = (xg in 0..4, tc in 0..7). Lane -> x (contiguous, conflict-free),
    // thread slides along t with a 26-wide register window.
    for (int task = w; task < 40; task += NWARP) {
        int xg = task % 5;
        int tc = task / 5;
        int x  = xg * 32 + lane;
        int t0 = tc * CHUNK;
        if (x < CPT_COLS) {
            float win[CHUNK + NTAP - 1];
#pragma unroll
            for (int j = 0; j < CHUNK + NTAP - 1; j++)
                win[j] = CPT[(t0 + j) * CPT_COLS + x];
#pragma unroll
            for (int i = 0; i < CHUNK; i++) {
                float acc = 0.0f;
#pragma unroll
                for (int k = 0; k < NTAP; k++) acc = fmaf(W[k], win[i + k], acc);
                V[(t0 + i) * V_COLS + (x + D_RAD)] = acc;
            }
        }
    }
    __syncthreads();

    // ---- Phase 3: convolve along x, tanh, coalesced write ----
    // out[s][t] = tanh( sum_k W[k] * V[t][s+k] )
    // Task = (sc in 0..7, tg in 0..3). Lane -> t (stride 139, odd -> conflict-free),
    // thread slides along s with a 26-wide register window.
    float* o = out + n * (S_IMG * S_IMG);
    for (int task = w; task < 32; task += NWARP) {
        int tg = task & 3;
        int sc = task >> 2;
        int t  = tg * 32 + lane;
        int s0 = sc * CHUNK;
        const float* base = &V[t * V_COLS + s0];
        float win[CHUNK + NTAP - 1];
#pragma unroll
        for (int j = 0; j < CHUNK + NTAP - 1; j++) win[j] = base[j];
#pragma unroll
        for (int i = 0; i < CHUNK; i++) {
            float acc = 0.0f;
#pragma unroll
            for (int k = 0; k < NTAP; k++) acc = fmaf(W[k], win[i + k], acc);
            o[(s0 + i) * S_IMG + t] = tanh_approx(acc);
        }
    }
}

extern "C" void kernel_launch(void* const* d_in, const int* in_sizes, int n_in,
                              void* d_out, int out_size) {
    const float* points = (const float*)d_in[0];
    float* out = (float*)d_out;
    size_t smem = (size_t)(CPT_SIZE + V_SIZE + 2 * P_PTS) * sizeof(float);
    cudaFuncSetAttribute(plotline2_kernel,
                         cudaFuncAttributeMaxDynamicSharedMemorySize, (int)smem);
    plotline2_kernel<<<N_IMG, THREADS, smem>>>(points, out);
}

// round 6
// speedup vs baseline: 1.7464x; 1.6880x over previous
#include <cuda_runtime.h>
#include <cuda_bf16.h>

// PlotLine2: histogram of rounded lerp points + separable 9-tap Gaussian conv.
// R5: run-length-deduped shared atomics, minimal zeroing, 1024 threads,
// 3-way accumulator trees, taps |d|<=4 (|d|=5 contributes <2e-7 abs).

#define N_IMG    128
#define P_PTS    16
#define S_IMG    128
#define D_RAD    4
#define NTAP     9
#define CPT_ROWS 137                 // y_pad = y + 4 : rows 0..136 (y=0..128 -> 4..132)
#define CPT_COLS 129                 // x = 0..128
#define CPT_SIZE 17676               // 137*129 = 17673, padded to /4
#define V_COLS   137                 // x_pad = x + 4 (odd stride -> conflict-free)
#define V_SIZE   (128 * V_COLS)      // 17536
#define THREADS  1024
#define NWARP    (THREADS / 32)
#define CHUNK    8
#define WLEN     (CHUNK + NTAP - 1)  // 16

__device__ __forceinline__ float tanh_approx(float x) {
    float r;
    asm("tanh.approx.f32 %0, %1;" : "=f"(r) : "f"(x));
    return r;
}

__global__ __launch_bounds__(THREADS, 1)
void plotline2_kernel(const float* __restrict__ points, float* __restrict__ out) {
    extern __shared__ float sm[];
    float* CPT = sm;                 // [CPT_ROWS][CPT_COLS] histogram (row = y+4)
    float* V   = sm + CPT_SIZE;      // [128][V_COLS] y-convolved (col = x+4)
    float* pts = V + V_SIZE;         // [2*P_PTS]

    const int tid  = threadIdx.x;
    const int n    = blockIdx.x;
    const int w    = tid >> 5;
    const int lane = tid & 31;

    // ---- Phase 0: zero CPT (vectorized) + V pad columns only; stage points ----
    {
        float4* z = (float4*)CPT;
        const float4 z4 = make_float4(0.f, 0.f, 0.f, 0.f);
        for (int i = tid; i < CPT_SIZE / 4; i += THREADS) z[i] = z4;
    }
    // V pad columns: 0..3 and 133..136 (read by phase 3, never written by phase 2)
    if (tid < 1024) {
        int t = tid >> 3;            // 0..127
        int c = tid & 7;             // 0..7
        int col = (c < 4) ? c : (129 + c);   // 0..3, 133..136
        V[t * V_COLS + col] = 0.0f;
    }
    if (tid < 2 * P_PTS) pts[tid] = points[n * (2 * P_PTS) + tid];
    __syncthreads();

    // ---- Phase 1: run-length-deduped histogram of rounded lerp points ----
    // Exact ref arithmetic: t=i/128 exact, non-contracted mul/mul/add, rintf (RNE).
    if (tid < 240) {
        int j0 = tid * 8;
        int lastAddr = -1;
        float cnt = 0.0f;
#pragma unroll
        for (int jj = 0; jj < 8; jj++) {
            int j   = j0 + jj;
            int seg = j >> 7;
            int i   = j & (S_IMG - 1);
            float t   = (float)i * (1.0f / (float)S_IMG);
            float omt = 1.0f - t;
            float x = __fadd_rn(__fmul_rn(omt, pts[seg * 2 + 0]), __fmul_rn(t, pts[seg * 2 + 2]));
            float y = __fadd_rn(__fmul_rn(omt, pts[seg * 2 + 1]), __fmul_rn(t, pts[seg * 2 + 3]));
            int ix = (int)rintf(x);          // 0..128
            int iy = (int)rintf(y);          // 0..128
            int addr = (iy + D_RAD) * CPT_COLS + ix;
            if (addr == lastAddr) {
                cnt += 1.0f;
            } else {
                if (lastAddr >= 0) atomicAdd(&CPT[lastAddr], cnt);
                lastAddr = addr;
                cnt = 1.0f;
            }
        }
        atomicAdd(&CPT[lastAddr], cnt);
    }
    __syncthreads();

    // Gaussian taps exp(-d^2), d = -4..4 (compile-time constants -> FFMA immediates)
    const float W[NTAP] = {
        1.1253517471925912e-7f, 1.2340980408667956e-4f, 1.8315638888734179e-2f,
        0.36787944117144233f,   1.0f,
        0.36787944117144233f,   1.8315638888734179e-2f, 1.2340980408667956e-4f,
        1.1253517471925912e-7f
    };

    // ---- Phase 2: convolve along y ----
    // V[t][x+4] = sum_k W[k] * CPT[t+k][x];  lane -> x (contiguous), slide along t.
    // tasks: xg in 0..4, tc in 0..15  -> 80 tasks over 32 warps
    for (int task = w; task < 80; task += NWARP) {
        int xg = task % 5;
        int tc = task / 5;
        int x  = xg * 32 + lane;
        int t0 = tc * CHUNK;
        if (x < CPT_COLS) {
            float win[WLEN];
#pragma unroll
            for (int j = 0; j < WLEN; j++)
                win[j] = CPT[(t0 + j) * CPT_COLS + x];
#pragma unroll
            for (int i = 0; i < CHUNK; i++) {
                float a0 = __fmul_rn(W[0], win[i + 0]);
                float a1 = __fmul_rn(W[1], win[i + 1]);
                float a2 = __fmul_rn(W[2], win[i + 2]);
                a0 = fmaf(W[3], win[i + 3], a0);
                a1 = fmaf(W[4], win[i + 4], a1);
                a2 = fmaf(W[5], win[i + 5], a2);
                a0 = fmaf(W[6], win[i + 6], a0);
                a1 = fmaf(W[7], win[i + 7], a1);
                a2 = fmaf(W[8], win[i + 8], a2);
                V[(t0 + i) * V_COLS + (x + D_RAD)] = (a0 + a1) + a2;
            }
        }
    }
    __syncthreads();

    // ---- Phase 3: convolve along x, tanh, coalesced write ----
    // out[s][t] = tanh( sum_k W[k] * V[t][s+k] );  lane -> t (stride 137, odd).
    // tasks: tg in 0..3, sc in 0..15 -> 64 tasks over 32 warps (2 each)
    float* o = out + n * (S_IMG * S_IMG);
    for (int task = w; task < 64; task += NWARP) {
        int tg = task & 3;
        int sc = task >> 2;
        int t  = tg * 32 + lane;
        int s0 = sc * CHUNK;
        const float* base = &V[t * V_COLS + s0];
        float win[WLEN];
#pragma unroll
        for (int j = 0; j < WLEN; j++) win[j] = base[j];
#pragma unroll
        for (int i = 0; i < CHUNK; i++) {
            float a0 = __fmul_rn(W[0], win[i + 0]);
            float a1 = __fmul_rn(W[1], win[i + 1]);
            float a2 = __fmul_rn(W[2], win[i + 2]);
            a0 = fmaf(W[3], win[i + 3], a0);
            a1 = fmaf(W[4], win[i + 4], a1);
            a2 = fmaf(W[5], win[i + 5], a2);
            a0 = fmaf(W[6], win[i + 6], a0);
            a1 = fmaf(W[7], win[i + 7], a1);
            a2 = fmaf(W[8], win[i + 8], a2);
            o[(s0 + i) * S_IMG + t] = tanh_approx((a0 + a1) + a2);
        }
    }
}

extern "C" void kernel_launch(void* const* d_in, const int* in_sizes, int n_in,
                              void* d_out, int out_size) {
    const float* points = (const float*)d_in[0];
    float* out = (float*)d_out;
    size_t smem = (size_t)(CPT_SIZE + V_SIZE + 2 * P_PTS) * sizeof(float);
    cudaFuncSetAttribute(plotline2_kernel,
                         cudaFuncAttributeMaxDynamicSharedMemorySize, (int)smem);
    plotline2_kernel<<<N_IMG, THREADS, smem>>>(points, out);
}

// round 7
// speedup vs baseline: 1.7934x; 1.0269x over previous
#include <cuda_runtime.h>
#include <cuda_bf16.h>

// PlotLine2: histogram of rounded lerp points + separable 7-tap Gaussian conv.
// R6: split each image across 2 CTAs along y (grid=256, 71KB smem -> 2 CTAs/SM)
// so phases of co-resident CTAs overlap; 7 taps (|d|<=3).

#define N_IMG    128
#define P_PTS    16
#define S_IMG    128
#define D_RAD    3
#define NTAP     7
#define C_COLS   129                  // x = 0..128
#define C_ROWS   70                   // local iy rows: iy in [64h-3, 64h+66]
#define C_SIZE   9032                 // 70*129 = 9030, padded to /4
#define V_STRIDE 135                  // cols c = x+3 (0..134), odd -> conflict-free
#define V_ROWS   64                   // local t rows
#define V_SIZE   (V_ROWS * V_STRIDE)  // 8640
#define THREADS  512
#define NWARP    (THREADS / 32)
#define CHUNK    8
#define WLEN     (CHUNK + NTAP - 1)   // 14

__device__ __forceinline__ float tanh_approx(float x) {
    float r;
    asm("tanh.approx.f32 %0, %1;" : "=f"(r) : "f"(x));
    return r;
}

__global__ __launch_bounds__(THREADS, 2)
void plotline2_kernel(const float* __restrict__ points, float* __restrict__ out) {
    extern __shared__ float sm[];
    float* C   = sm;              // [C_ROWS][C_COLS] histogram slice (row = iy - (64*half - 3))
    float* V   = sm + C_SIZE;     // [V_ROWS][V_STRIDE] y-convolved slice (col = x+3)
    float* pts = V + V_SIZE;      // [2*P_PTS]

    const int tid  = threadIdx.x;
    const int n    = blockIdx.x >> 1;
    const int half = blockIdx.x & 1;   // t (= y) range [64*half, 64*half+63]
    const int w    = tid >> 5;
    const int lane = tid & 31;

    // ---- Phase 0: zero C (vectorized) + V pad cols; stage control points ----
    {
        float4* z = (float4*)C;
        const float4 z4 = make_float4(0.f, 0.f, 0.f, 0.f);
        for (int i = tid; i < C_SIZE / 4; i += THREADS) z[i] = z4;
    }
    if (tid < V_ROWS * 6) {            // pad cols 0..2 and 132..134
        int t  = tid / 6;
        int c6 = tid % 6;
        int c  = (c6 < 3) ? c6 : (129 + c6);
        V[t * V_STRIDE + c] = 0.0f;
    }
    if (tid < 2 * P_PTS) pts[tid] = points[n * (2 * P_PTS) + tid];
    __syncthreads();

    // ---- Phase 1: run-length-deduped histogram (filtered to this CTA's iy range) ----
    // Exact ref arithmetic: t=i/128 exact, non-contracted mul/mul/add, rintf (RNE).
    if (tid < 480) {
        const int rbase = 64 * half - 3;       // iy at local row 0
        int j0 = tid * 4;
        int lastAddr = -1;
        float cnt = 0.0f;
#pragma unroll
        for (int jj = 0; jj < 4; jj++) {
            int j   = j0 + jj;
            int seg = j >> 7;
            int i   = j & (S_IMG - 1);
            float t   = (float)i * (1.0f / (float)S_IMG);
            float omt = 1.0f - t;
            float x = __fadd_rn(__fmul_rn(omt, pts[seg * 2 + 0]), __fmul_rn(t, pts[seg * 2 + 2]));
            float y = __fadd_rn(__fmul_rn(omt, pts[seg * 2 + 1]), __fmul_rn(t, pts[seg * 2 + 3]));
            int ix = (int)rintf(x);            // 0..128
            int iy = (int)rintf(y);            // 0..128
            int row = iy - rbase;
            if ((unsigned)row < (unsigned)C_ROWS) {
                int addr = row * C_COLS + ix;
                if (addr == lastAddr) {
                    cnt += 1.0f;
                } else {
                    if (lastAddr >= 0) atomicAdd(&C[lastAddr], cnt);
                    lastAddr = addr;
                    cnt = 1.0f;
                }
            }
        }
        if (lastAddr >= 0) atomicAdd(&C[lastAddr], cnt);
    }
    __syncthreads();

    // Gaussian taps exp(-d^2), d = -3..3 (compile-time -> FFMA immediates)
    const float W[NTAP] = {
        1.2340980408667956e-4f, 1.8315638888734179e-2f, 0.36787944117144233f,
        1.0f,
        0.36787944117144233f,   1.8315638888734179e-2f, 1.2340980408667956e-4f
    };

    // ---- Phase 2: convolve along y ----
    // V[t][x+3] = sum_k W[k] * C[t+k][x]   (local rows; lane -> x, slide along t)
    // tasks: xg in 0..4, tc in 0..7 -> 40 tasks over 16 warps
    for (int task = w; task < 40; task += NWARP) {
        int xg = task % 5;
        int tc = task / 5;
        int x  = xg * 32 + lane;
        int t0 = tc * CHUNK;
        if (x < C_COLS) {
            float win[WLEN];
#pragma unroll
            for (int j = 0; j < WLEN; j++)
                win[j] = C[(t0 + j) * C_COLS + x];
#pragma unroll
            for (int i = 0; i < CHUNK; i++) {
                float a0 = __fmul_rn(W[0], win[i + 0]);
                float a1 = __fmul_rn(W[1], win[i + 1]);
                float a2 = __fmul_rn(W[2], win[i + 2]);
                a0 = fmaf(W[3], win[i + 3], a0);
                a1 = fmaf(W[4], win[i + 4], a1);
                a2 = fmaf(W[5], win[i + 5], a2);
                a0 = fmaf(W[6], win[i + 6], a0);
                V[(t0 + i) * V_STRIDE + (x + D_RAD)] = (a0 + a1) + a2;
            }
        }
    }
    __syncthreads();

    // ---- Phase 3: convolve along x, tanh, coalesced write ----
    // out[s][64*half + t] = tanh( sum_k W[k] * V[t][s+k] )  (V col = x+3)
    // tasks: tg in 0..1, sc in 0..15 -> 32 tasks over 16 warps
    float* o = out + n * (S_IMG * S_IMG) + 64 * half;
    for (int task = w; task < 32; task += NWARP) {
        int tg = task & 1;
        int sc = task >> 1;
        int t  = tg * 32 + lane;
        int s0 = sc * CHUNK;
        const float* base = &V[t * V_STRIDE + s0];
        float win[WLEN];
#pragma unroll
        for (int j = 0; j < WLEN; j++) win[j] = base[j];
#pragma unroll
        for (int i = 0; i < CHUNK; i++) {
            float a0 = __fmul_rn(W[0], win[i + 0]);
            float a1 = __fmul_rn(W[1], win[i + 1]);
            float a2 = __fmul_rn(W[2], win[i + 2]);
            a0 = fmaf(W[3], win[i + 3], a0);
            a1 = fmaf(W[4], win[i + 4], a1);
            a2 = fmaf(W[5], win[i + 5], a2);
            a0 = fmaf(W[6], win[i + 6], a0);
            o[(s0 + i) * S_IMG + t] = tanh_approx((a0 + a1) + a2);
        }
    }
}

extern "C" void kernel_launch(void* const* d_in, const int* in_sizes, int n_in,
                              void* d_out, int out_size) {
    const float* points = (const float*)d_in[0];
    float* out = (float*)d_out;
    size_t smem = (size_t)(C_SIZE + V_SIZE + 2 * P_PTS) * sizeof(float);
    cudaFuncSetAttribute(plotline2_kernel,
                         cudaFuncAttributeMaxDynamicSharedMemorySize, (int)smem);
    plotline2_kernel<<<2 * N_IMG, THREADS, smem>>>(points, out);
}